// round 2
// baseline (speedup 1.0000x reference)
#include <cuda_runtime.h>
#include <cstdint>

#define NN 100000
#define NE 1600000
#define DD 128

// ---------------- scratch (static device globals; no allocation) ----------------
__device__ float g_hn[NN * DD];     // (h @ W) * src_norm  (messages)
__device__ float g_agg[NN * DD];    // scatter-add accumulator
__device__ float g_outdeg[NN];
__device__ float g_indeg[NN];
__device__ float g_srcnorm[NN];
__device__ float g_dstnorm[NN];

// ---------------- small utility kernels ----------------
__global__ void zero_degs_kernel(int n) {
    int i = blockIdx.x * blockDim.x + threadIdx.x;
    if (i < n) { g_outdeg[i] = 0.f; g_indeg[i] = 0.f; }
}

__global__ void degree_kernel(const int* __restrict__ src,
                              const int* __restrict__ dst, int E) {
    int i = blockIdx.x * blockDim.x + threadIdx.x;
    if (i < E) {
        atomicAdd(&g_outdeg[src[i]], 1.0f);
        atomicAdd(&g_indeg[dst[i]], 1.0f);
    }
}

__global__ void norm_kernel(int n) {
    int i = blockIdx.x * blockDim.x + threadIdx.x;
    if (i < n) {
        g_srcnorm[i] = rsqrtf(fmaxf(g_outdeg[i], 1.0f));
        g_dstnorm[i] = rsqrtf(fmaxf(g_indeg[i], 1.0f));
    }
}

__global__ void zero_agg_kernel() {
    int i = blockIdx.x * blockDim.x + threadIdx.x;   // over NN*DD/4 float4s
    ((float4*)g_agg)[i] = make_float4(0.f, 0.f, 0.f, 0.f);
}

// ---------------- GEMM: out(g_hn) = transform(A) @ W, rows scaled by src_norm ----
// MODE 0: A used raw (layer 1, A = feats)
// MODE 1: A element (r,k) -> relu(A[r][k] * dst_norm[r] + prevB[k])   (A = g_agg)
// Block: 128 rows x 128 cols, 256 threads, 8x8 per thread, BK=16.
template <int MODE>
__global__ void __launch_bounds__(256)
gemm_kernel(const float* __restrict__ A, const float* __restrict__ W,
            const float* __restrict__ prevB, int M) {
    __shared__ float As[16][132];      // [k][m], padded; rows stay 16B-aligned
    __shared__ float Bs[16 * 128];     // [k][n]

    const int t  = threadIdx.x;
    const int tx = t & 15;             // 16 thread-cols
    const int ty = t >> 4;             // 16 thread-rows
    const int row0 = blockIdx.x * 128;

    float acc[8][8];
#pragma unroll
    for (int i = 0; i < 8; i++)
#pragma unroll
        for (int j = 0; j < 8; j++) acc[i][j] = 0.f;

    for (int kk = 0; kk < 128; kk += 16) {
        // load + transform A tile (128 x 16) -> As[k][m]
#pragma unroll
        for (int i = 0; i < 8; i++) {
            int idx = t + i * 256;
            int m = idx >> 4, k = idx & 15;
            int gr = row0 + m;
            float v = 0.f;
            if (gr < M) {
                v = A[gr * 128 + kk + k];
                if (MODE == 1)
                    v = fmaxf(fmaf(v, g_dstnorm[gr], prevB[kk + k]), 0.f);
            }
            As[k][m] = v;
        }
        // load W tile (16 x 128) -> Bs[k][n]
#pragma unroll
        for (int i = 0; i < 8; i++) {
            int idx = t + i * 256;
            int k = idx >> 7, n = idx & 127;
            Bs[k * 128 + n] = W[(kk + k) * 128 + n];
        }
        __syncthreads();

#pragma unroll
        for (int k = 0; k < 16; k++) {
            float4 a0 = *(const float4*)&As[k][ty * 8];
            float4 a1 = *(const float4*)&As[k][ty * 8 + 4];
            float4 b0 = *(const float4*)&Bs[k * 128 + tx * 4];
            float4 b1 = *(const float4*)&Bs[k * 128 + 64 + tx * 4];
            float av[8] = {a0.x, a0.y, a0.z, a0.w, a1.x, a1.y, a1.z, a1.w};
            float bv[8] = {b0.x, b0.y, b0.z, b0.w, b1.x, b1.y, b1.z, b1.w};
#pragma unroll
            for (int i = 0; i < 8; i++)
#pragma unroll
                for (int j = 0; j < 8; j++)
                    acc[i][j] = fmaf(av[i], bv[j], acc[i][j]);
        }
        __syncthreads();
    }

    // epilogue: scale rows by src_norm, write messages
#pragma unroll
    for (int i = 0; i < 8; i++) {
        int gr = row0 + ty * 8 + i;
        if (gr < M) {
            float s = g_srcnorm[gr];
            float4 o0 = make_float4(acc[i][0] * s, acc[i][1] * s,
                                    acc[i][2] * s, acc[i][3] * s);
            float4 o1 = make_float4(acc[i][4] * s, acc[i][5] * s,
                                    acc[i][6] * s, acc[i][7] * s);
            *(float4*)&g_hn[gr * 128 + tx * 4] = o0;
            *(float4*)&g_hn[gr * 128 + 64 + tx * 4] = o1;
        }
    }
}

// ---------------- edge scatter: one warp per edge, red.global.add.v4.f32 --------
__global__ void __launch_bounds__(256)
scatter_kernel(const int* __restrict__ src,
               const int* __restrict__ dst, int E) {
    int e = blockIdx.x * 8 + (threadIdx.x >> 5);
    if (e >= E) return;
    int lane = threadIdx.x & 31;
    int s = __ldg(&src[e]);
    int d = __ldg(&dst[e]);
    float4 v = *(const float4*)&g_hn[s * 128 + lane * 4];
    float* p = &g_agg[d * 128 + lane * 4];
    asm volatile("red.global.add.v4.f32 [%0], {%1,%2,%3,%4};"
                 :: "l"(p), "f"(v.x), "f"(v.y), "f"(v.z), "f"(v.w)
                 : "memory");
}

// ---------------- final epilogue: out = agg * dst_norm + b3 (no relu) -----------
__global__ void final_kernel(const float* __restrict__ b3, float* __restrict__ out) {
    int i = blockIdx.x * blockDim.x + threadIdx.x;   // over NN*DD/4 float4s
    int base = i * 4;
    int row = base >> 7;
    int col = base & 127;
    float dn = g_dstnorm[row];
    float4 a = ((const float4*)g_agg)[i];
    float4 b = *(const float4*)&b3[col];
    float4 o = make_float4(fmaf(a.x, dn, b.x), fmaf(a.y, dn, b.y),
                           fmaf(a.z, dn, b.z), fmaf(a.w, dn, b.w));
    ((float4*)out)[i] = o;
}

// ---------------- launch ----------------
extern "C" void kernel_launch(void* const* d_in, const int* in_sizes, int n_in,
                              void* d_out, int out_size) {
    const float* feats = (const float*)d_in[0];
    const float* W1 = (const float*)d_in[1];
    const float* b1 = (const float*)d_in[2];
    const float* W2 = (const float*)d_in[3];
    const float* b2 = (const float*)d_in[4];
    const float* W3 = (const float*)d_in[5];
    const float* b3 = (const float*)d_in[6];
    const int* src = (const int*)d_in[7];     // JAX x64 disabled -> int32
    const int* dst = (const int*)d_in[8];
    float* out = (float*)d_out;

    const int M = in_sizes[0] / DD;   // 100000
    const int E = in_sizes[7];        // 1600000

    float* aggp = nullptr;
    cudaGetSymbolAddress((void**)&aggp, g_agg);

    const int nb_node  = (M + 255) / 256;
    const int nb_edge  = (E + 255) / 256;
    const int nb_gemm  = (M + 127) / 128;
    const int nb_warp  = (E + 7) / 8;          // one warp per edge, 8 warps/block
    const int nb_vec4  = (M * DD / 4 + 255) / 256;

    // degrees + norms
    zero_degs_kernel<<<nb_node, 256>>>(M);
    degree_kernel<<<nb_edge, 256>>>(src, dst, E);
    norm_kernel<<<nb_node, 256>>>(M);

    // layer 1
    gemm_kernel<0><<<nb_gemm, 256>>>(feats, W1, b1, M);
    zero_agg_kernel<<<nb_vec4, 256>>>();
    scatter_kernel<<<nb_warp, 256>>>(src, dst, E);

    // layer 2 (input transform: *dst_norm + b1, relu)
    gemm_kernel<1><<<nb_gemm, 256>>>(aggp, W2, b1, M);
    zero_agg_kernel<<<nb_vec4, 256>>>();
    scatter_kernel<<<nb_warp, 256>>>(src, dst, E);

    // layer 3 (input transform: *dst_norm + b2, relu)
    gemm_kernel<1><<<nb_gemm, 256>>>(aggp, W3, b2, M);
    zero_agg_kernel<<<nb_vec4, 256>>>();
    scatter_kernel<<<nb_warp, 256>>>(src, dst, E);

    // final: out = agg * dst_norm + b3
    final_kernel<<<nb_vec4, 256>>>(b3, out);
}

// round 3
// speedup vs baseline: 2.1815x; 2.1815x over previous
#include <cuda_runtime.h>
#include <cstdint>

#define NN 100000
#define NE 1600000
#define DD 128
#define SCAN_B 512                       // elems per scan block
#define NSCAN ((NN + SCAN_B - 1) / SCAN_B)   // 196

// ---------------- scratch (static device globals) ----------------
__device__ float g_hn[NN * DD];     // (h @ W) * src_norm  (messages)
__device__ float g_h[NN * DD];      // aggregated + transformed activations
__device__ int   g_cin[NN];
__device__ int   g_cout[NN];
__device__ int   g_fill[NN];
__device__ int   g_off[NN + 1];     // CSR row offsets (by dst)
__device__ int   g_csr[NE];         // src ids sorted by dst
__device__ float g_srcnorm[NN];
__device__ float g_dstnorm[NN];
__device__ int   g_bsum[NSCAN];
__device__ int   g_bpre[NSCAN];

// ---------------- CSR build ----------------
__global__ void k_zero(int n) {
    int i = blockIdx.x * blockDim.x + threadIdx.x;
    if (i < n) { g_cin[i] = 0; g_cout[i] = 0; g_fill[i] = 0; }
}

__global__ void k_count(const int* __restrict__ src,
                        const int* __restrict__ dst, int E) {
    int i = blockIdx.x * blockDim.x + threadIdx.x;
    if (i < E) {
        atomicAdd(&g_cout[src[i]], 1);
        atomicAdd(&g_cin[dst[i]], 1);
    }
}

__global__ void k_norm(int n) {
    int i = blockIdx.x * blockDim.x + threadIdx.x;
    if (i < n) {
        g_srcnorm[i] = rsqrtf((float)max(g_cout[i], 1));
        g_dstnorm[i] = rsqrtf((float)max(g_cin[i], 1));
    }
}

// level-1 scan: each block scans SCAN_B counts -> exclusive prefix + block sum
__global__ void k_scan1(int n) {
    __shared__ int s[SCAN_B];
    int t = threadIdx.x;
    int g = blockIdx.x * SCAN_B + t;
    int v = (g < n) ? g_cin[g] : 0;
    s[t] = v;
    __syncthreads();
    // Hillis-Steele inclusive scan
    for (int o = 1; o < SCAN_B; o <<= 1) {
        int x = (t >= o) ? s[t - o] : 0;
        __syncthreads();
        s[t] += x;
        __syncthreads();
    }
    if (g < n) g_off[g] = s[t] - v;          // exclusive
    if (t == SCAN_B - 1) g_bsum[blockIdx.x] = s[t];
}

__global__ void k_scan2(int nb, int n) {
    if (threadIdx.x == 0 && blockIdx.x == 0) {
        int run = 0;
        for (int b = 0; b < nb; b++) { g_bpre[b] = run; run += g_bsum[b]; }
        g_off[n] = run;
    }
}

__global__ void k_scan3(int n) {
    int g = blockIdx.x * blockDim.x + threadIdx.x;
    if (g < n) g_off[g] += g_bpre[g / SCAN_B];
}

__global__ void k_fill(const int* __restrict__ src,
                       const int* __restrict__ dst, int E) {
    int e = blockIdx.x * blockDim.x + threadIdx.x;
    if (e < E) {
        int d = dst[e];
        int p = g_off[d] + atomicAdd(&g_fill[d], 1);
        g_csr[p] = src[e];
    }
}

// ---------------- GEMM: g_hn = A @ W, rows scaled by src_norm ----------------
// Block: 128 rows x 128 cols, 256 threads, 8x8 per thread, BK=16.
__global__ void __launch_bounds__(256)
gemm_kernel(const float* __restrict__ A, const float* __restrict__ W, int M) {
    __shared__ float As[16][132];
    __shared__ float Bs[16 * 128];

    const int t  = threadIdx.x;
    const int tx = t & 15;
    const int ty = t >> 4;
    const int row0 = blockIdx.x * 128;

    float acc[8][8];
#pragma unroll
    for (int i = 0; i < 8; i++)
#pragma unroll
        for (int j = 0; j < 8; j++) acc[i][j] = 0.f;

    for (int kk = 0; kk < 128; kk += 16) {
#pragma unroll
        for (int i = 0; i < 8; i++) {
            int idx = t + i * 256;
            int m = idx >> 4, k = idx & 15;
            int gr = row0 + m;
            As[k][m] = (gr < M) ? A[gr * 128 + kk + k] : 0.f;
        }
#pragma unroll
        for (int i = 0; i < 8; i++) {
            int idx = t + i * 256;
            int k = idx >> 7, n = idx & 127;
            Bs[k * 128 + n] = W[(kk + k) * 128 + n];
        }
        __syncthreads();

#pragma unroll
        for (int k = 0; k < 16; k++) {
            float4 a0 = *(const float4*)&As[k][ty * 8];
            float4 a1 = *(const float4*)&As[k][ty * 8 + 4];
            float4 b0 = *(const float4*)&Bs[k * 128 + tx * 4];
            float4 b1 = *(const float4*)&Bs[k * 128 + 64 + tx * 4];
            float av[8] = {a0.x, a0.y, a0.z, a0.w, a1.x, a1.y, a1.z, a1.w};
            float bv[8] = {b0.x, b0.y, b0.z, b0.w, b1.x, b1.y, b1.z, b1.w};
#pragma unroll
            for (int i = 0; i < 8; i++)
#pragma unroll
                for (int j = 0; j < 8; j++)
                    acc[i][j] = fmaf(av[i], bv[j], acc[i][j]);
        }
        __syncthreads();
    }

#pragma unroll
    for (int i = 0; i < 8; i++) {
        int gr = row0 + ty * 8 + i;
        if (gr < M) {
            float s = g_srcnorm[gr];
            float4 o0 = make_float4(acc[i][0] * s, acc[i][1] * s,
                                    acc[i][2] * s, acc[i][3] * s);
            float4 o1 = make_float4(acc[i][4] * s, acc[i][5] * s,
                                    acc[i][6] * s, acc[i][7] * s);
            *(float4*)&g_hn[gr * 128 + tx * 4] = o0;
            *(float4*)&g_hn[gr * 128 + 64 + tx * 4] = o1;
        }
    }
}

// ---------------- CSR aggregation: one warp per dst node --------------------
// out[d] = act( (sum_{e in in(d)} g_hn[src(e)]) * dst_norm[d] + bias )
template <int RELU>
__global__ void __launch_bounds__(256)
agg_kernel(const float* __restrict__ bias, float* __restrict__ out, int n) {
    int w = blockIdx.x * 8 + (threadIdx.x >> 5);
    if (w >= n) return;
    int lane = threadIdx.x & 31;

    int start = g_off[w];
    int end   = g_off[w + 1];

    float4 acc = make_float4(0.f, 0.f, 0.f, 0.f);

    for (int i = start; i < end; i += 32) {
        int myid = (i + lane < end) ? g_csr[i + lane] : 0;
        int cnt = min(32, end - i);
#pragma unroll 4
        for (int j = 0; j < cnt; j++) {
            int s = __shfl_sync(0xffffffffu, myid, j);
            const float4 v = *(const float4*)&g_hn[(size_t)s * 128 + lane * 4];
            acc.x += v.x; acc.y += v.y; acc.z += v.z; acc.w += v.w;
        }
    }

    float dn = g_dstnorm[w];
    float4 b = *(const float4*)&bias[lane * 4];
    float4 o = make_float4(fmaf(acc.x, dn, b.x), fmaf(acc.y, dn, b.y),
                           fmaf(acc.z, dn, b.z), fmaf(acc.w, dn, b.w));
    if (RELU) {
        o.x = fmaxf(o.x, 0.f); o.y = fmaxf(o.y, 0.f);
        o.z = fmaxf(o.z, 0.f); o.w = fmaxf(o.w, 0.f);
    }
    *(float4*)&out[(size_t)w * 128 + lane * 4] = o;
}

// ---------------- launch ----------------
extern "C" void kernel_launch(void* const* d_in, const int* in_sizes, int n_in,
                              void* d_out, int out_size) {
    const float* feats = (const float*)d_in[0];
    const float* W1 = (const float*)d_in[1];
    const float* b1 = (const float*)d_in[2];
    const float* W2 = (const float*)d_in[3];
    const float* b2 = (const float*)d_in[4];
    const float* W3 = (const float*)d_in[5];
    const float* b3 = (const float*)d_in[6];
    const int* src = (const int*)d_in[7];
    const int* dst = (const int*)d_in[8];
    float* out = (float*)d_out;

    const int M = in_sizes[0] / DD;   // 100000
    const int E = in_sizes[7];        // 1600000

    float* hp = nullptr;
    cudaGetSymbolAddress((void**)&hp, g_h);

    const int nb_node = (M + 255) / 256;
    const int nb_edge = (E + 255) / 256;
    const int nb_gemm = (M + 127) / 128;
    const int nb_agg  = (M + 7) / 8;            // warp per node, 8 warps/block
    const int nscan   = (M + SCAN_B - 1) / SCAN_B;

    // ---- build norms + CSR (by dst) ----
    k_zero<<<nb_node, 256>>>(M);
    k_count<<<nb_edge, 256>>>(src, dst, E);
    k_norm<<<nb_node, 256>>>(M);
    k_scan1<<<nscan, SCAN_B>>>(M);
    k_scan2<<<1, 32>>>(nscan, M);
    k_scan3<<<nb_node, 256>>>(M);
    k_fill<<<nb_edge, 256>>>(src, dst, E);

    // ---- layer 1 ----
    gemm_kernel<<<nb_gemm, 256>>>(feats, W1, M);
    agg_kernel<1><<<nb_agg, 256>>>(b1, hp, M);
    // ---- layer 2 ----
    gemm_kernel<<<nb_gemm, 256>>>(hp, W2, M);
    agg_kernel<1><<<nb_agg, 256>>>(b2, hp, M);
    // ---- layer 3 ----
    gemm_kernel<<<nb_gemm, 256>>>(hp, W3, M);
    agg_kernel<0><<<nb_agg, 256>>>(b3, out, M);
}